// round 1
// baseline (speedup 1.0000x reference)
#include <cuda_runtime.h>
#include <cuda_bf16.h>

#define NN 262144
#define DD 1024
#define GG 1024
#define NA 17
#define EPS 1e-5f

// ---------------- scratch (device globals; no allocation allowed) -------------
__device__ int   d_starts[GG + 1];
__device__ float d_stats[GG * 56];          // per graph: a0[17], a1[17], c2[17], n0, n1 (53 used)
__device__ float d_pooled[GG * DD];         // 4 MB
__device__ float d_r0[GG * (DD / 2)];       // 2 MB
__device__ float d_h0[GG * (DD / 2)];
__device__ float d_r1[GG * (DD / 4)];
__device__ float d_h1[GG * (DD / 4)];

// ---------------- K1: segment starts via binary search (robust to empties) ----
__global__ void k_find_starts(const int* __restrict__ batch) {
    int i = blockIdx.x * blockDim.x + threadIdx.x;
    if (i > GG) return;
    int lo = 0, hi = NN;
    while (lo < hi) {
        int mid = (lo + hi) >> 1;
        if (batch[mid] < i) lo = mid + 1; else hi = mid;
    }
    d_starts[i] = lo;
}

// ---------------- K2: per-graph attr stats ------------------------------------
__global__ void k_stats(const float* __restrict__ attr, const int* __restrict__ ntype) {
    int gph = blockIdx.x;
    int s0 = d_starts[gph], s1 = d_starts[gph + 1];

    float a0[NA], a1[NA], c2[NA];
    #pragma unroll
    for (int k = 0; k < NA; k++) { a0[k] = 0.f; a1[k] = 0.f; c2[k] = 0.f; }
    float n0 = 0.f, n1 = 0.f;

    for (int r = s0 + threadIdx.x; r < s1; r += blockDim.x) {
        int t = ntype[r];
        const float* ar = attr + (long)r * NA;
        float av[NA];
        #pragma unroll
        for (int k = 0; k < NA; k++) av[k] = ar[k];
        if (t == 0) {
            n0 += 1.f;
            #pragma unroll
            for (int k = 0; k < NA; k++) a0[k] += av[k];
        } else if (t == 1) {
            n1 += 1.f;
            #pragma unroll
            for (int k = 0; k < NA; k++) a1[k] += av[k];
        } else if (t == 2) {
            int idx = (int)av[0];
            idx = idx < 0 ? 0 : (idx > NA - 1 ? NA - 1 : idx);
            #pragma unroll
            for (int k = 0; k < NA; k++) c2[k] += (k == idx) ? 1.f : 0.f;
        }
    }

    __shared__ float s_acc[56];
    for (int j = threadIdx.x; j < 56; j += blockDim.x) s_acc[j] = 0.f;
    __syncthreads();

    int lane = threadIdx.x & 31;
    #pragma unroll
    for (int k = 0; k < NA; k++) {
        float v = a0[k];
        #pragma unroll
        for (int o = 16; o; o >>= 1) v += __shfl_xor_sync(0xffffffffu, v, o);
        if (lane == 0) atomicAdd(&s_acc[k], v);
        v = a1[k];
        #pragma unroll
        for (int o = 16; o; o >>= 1) v += __shfl_xor_sync(0xffffffffu, v, o);
        if (lane == 0) atomicAdd(&s_acc[NA + k], v);
        v = c2[k];
        #pragma unroll
        for (int o = 16; o; o >>= 1) v += __shfl_xor_sync(0xffffffffu, v, o);
        if (lane == 0) atomicAdd(&s_acc[2 * NA + k], v);
    }
    {
        float v = n0;
        #pragma unroll
        for (int o = 16; o; o >>= 1) v += __shfl_xor_sync(0xffffffffu, v, o);
        if (lane == 0) atomicAdd(&s_acc[51], v);
        v = n1;
        #pragma unroll
        for (int o = 16; o; o >>= 1) v += __shfl_xor_sync(0xffffffffu, v, o);
        if (lane == 0) atomicAdd(&s_acc[52], v);
    }
    __syncthreads();
    for (int j = threadIdx.x; j < 56; j += blockDim.x) d_stats[gph * 56 + j] = s_acc[j];
}

// ---------------- K3: segment sum of x + fused tiny emb GEMM + mean ----------
// One block per graph, 256 threads, each owns one float4 column group (1024 cols).
__global__ void k_pool(const float* __restrict__ x,
                       const float* __restrict__ netW, const float* __restrict__ netb,
                       const float* __restrict__ devW, const float* __restrict__ devb,
                       const float* __restrict__ pinE) {
    int gph = blockIdx.x;
    int s0 = d_starts[gph], s1 = d_starts[gph + 1];

    __shared__ float st[56];
    for (int j = threadIdx.x; j < 56; j += 256) st[j] = d_stats[gph * 56 + j];
    __syncthreads();

    int c4 = threadIdx.x; // column group [4*c4, 4*c4+4)
    const float4* x4 = (const float4*)x;
    float4 acc = make_float4(0.f, 0.f, 0.f, 0.f);

    int r = s0;
    #pragma unroll 4
    for (; r < s1; r++) {
        float4 v = x4[(long)r * 256 + c4];
        acc.x += v.x; acc.y += v.y; acc.z += v.z; acc.w += v.w;
    }

    // emb contribution
    const float4* nW4 = (const float4*)netW;
    const float4* dW4 = (const float4*)devW;
    const float4* pE4 = (const float4*)pinE;
    float4 e = make_float4(0.f, 0.f, 0.f, 0.f);
    #pragma unroll
    for (int k = 0; k < NA; k++) {
        float4 wn = nW4[k * 256 + c4];
        float4 wd = dW4[k * 256 + c4];
        float4 wp = pE4[k * 256 + c4];
        float a0 = st[k], a1 = st[NA + k], cc = st[2 * NA + k];
        e.x += a0 * wn.x + a1 * wd.x + cc * wp.x;
        e.y += a0 * wn.y + a1 * wd.y + cc * wp.y;
        e.z += a0 * wn.z + a1 * wd.z + cc * wp.z;
        e.w += a0 * wn.w + a1 * wd.w + cc * wp.w;
    }
    float n0 = st[51], n1 = st[52];
    float4 nb = ((const float4*)netb)[c4];
    float4 db = ((const float4*)devb)[c4];
    e.x += n0 * nb.x + n1 * db.x;
    e.y += n0 * nb.y + n1 * db.y;
    e.z += n0 * nb.z + n1 * db.z;
    e.w += n0 * nb.w + n1 * db.w;

    float inv = 1.f / fmaxf((float)(s1 - s0), 1.f);
    float4 o;
    o.x = (acc.x + e.x) * inv;
    o.y = (acc.y + e.y) * inv;
    o.z = (acc.z + e.z) * inv;
    o.w = (acc.w + e.w) * inv;
    ((float4*)d_pooled)[(long)gph * 256 + c4] = o;
}

// ---------------- K4: GEMM + bias + relu (fp32 SIMT, 64x64 tile) -------------
__global__ void k_gemm_bias_relu(const float* __restrict__ A, const float* __restrict__ W,
                                 const float* __restrict__ bias, float* __restrict__ C,
                                 int M, int N, int K) {
    __shared__ float As[16][64];
    __shared__ float Bs[16][68];
    int tx = threadIdx.x & 15, ty = threadIdx.x >> 4;
    int n0 = blockIdx.x * 64, m0 = blockIdx.y * 64;
    float acc[4][4] = {};

    for (int k0 = 0; k0 < K; k0 += 16) {
        for (int i = threadIdx.x; i < 64 * 16; i += 256) {
            int m = i >> 4, kk = i & 15;
            As[kk][m] = A[(long)(m0 + m) * K + k0 + kk];
        }
        for (int i = threadIdx.x; i < 16 * 64; i += 256) {
            int kk = i >> 6, n = i & 63;
            Bs[kk][n] = W[(long)(k0 + kk) * N + n0 + n];
        }
        __syncthreads();
        #pragma unroll
        for (int kk = 0; kk < 16; kk++) {
            float a[4], b[4];
            #pragma unroll
            for (int u = 0; u < 4; u++) a[u] = As[kk][ty * 4 + u];
            #pragma unroll
            for (int u = 0; u < 4; u++) b[u] = Bs[kk][tx * 4 + u];
            #pragma unroll
            for (int i = 0; i < 4; i++)
                #pragma unroll
                for (int j = 0; j < 4; j++)
                    acc[i][j] += a[i] * b[j];
        }
        __syncthreads();
    }
    #pragma unroll
    for (int i = 0; i < 4; i++) {
        int m = m0 + ty * 4 + i;
        #pragma unroll
        for (int j = 0; j < 4; j++) {
            int n = n0 + tx * 4 + j;
            float v = acc[i][j] + bias[n];
            C[(long)m * N + n] = v > 0.f ? v : 0.f;
        }
    }
}

// ---------------- K5: batchnorm over rows (per 64-column chunk) ---------------
__global__ void k_bn(const float* __restrict__ R, const float* __restrict__ g,
                     const float* __restrict__ b, float* __restrict__ H, int N) {
    const int M = GG;
    int c0 = blockIdx.x * 64;
    int c = threadIdx.x & 63;
    int rg = threadIdx.x >> 6;

    float sum = 0.f, sq = 0.f;
    for (int r = rg; r < M; r += 4) {
        float v = R[(long)r * N + c0 + c];
        sum += v; sq += v * v;
    }
    __shared__ float ssum[4][64], ssq[4][64];
    ssum[rg][c] = sum; ssq[rg][c] = sq;
    __syncthreads();
    __shared__ float smean[64], srstd[64];
    if (threadIdx.x < 64) {
        int cc = threadIdx.x;
        float s = ssum[0][cc] + ssum[1][cc] + ssum[2][cc] + ssum[3][cc];
        float q = ssq[0][cc] + ssq[1][cc] + ssq[2][cc] + ssq[3][cc];
        float m = s / (float)M;
        float var = q / (float)M - m * m;
        smean[cc] = m;
        srstd[cc] = rsqrtf(var + EPS);
    }
    __syncthreads();
    float gg = g[c0 + c], bb = b[c0 + c], mm = smean[c], rs = srstd[c];
    for (int r = rg; r < M; r += 4) {
        float v = R[(long)r * N + c0 + c];
        H[(long)r * N + c0 + c] = (v - mm) * rs * gg + bb;
    }
}

// ---------------- K6: fc2 (dot 256) + output assembly -------------------------
__global__ void k_head_out(const float* __restrict__ H, const float* __restrict__ w,
                           const float* __restrict__ b, const float* __restrict__ y_reg,
                           float* __restrict__ out, int out_size) {
    int warp = (blockIdx.x * blockDim.x + threadIdx.x) >> 5;
    int lane = threadIdx.x & 31;
    if (warp >= GG) return;
    float s = 0.f;
    #pragma unroll
    for (int k = lane; k < DD / 4; k += 32) s += H[(long)warp * (DD / 4) + k] * w[k];
    #pragma unroll
    for (int o = 16; o; o >>= 1) s += __shfl_xor_sync(0xffffffffu, s, o);
    if (lane == 0) {
        out[warp] = s + b[0];
        if (out_size >= 2 * GG) out[GG + warp] = y_reg[warp];
    }
}

// ---------------- launch ------------------------------------------------------
extern "C" void kernel_launch(void* const* d_in, const int* in_sizes, int n_in,
                              void* d_out, int out_size) {
    const float* x        = (const float*)d_in[0];
    const float* nattr    = (const float*)d_in[1];
    const int*   ntype    = (const int*)d_in[2];
    const int*   batch    = (const int*)d_in[3];
    const float* y_reg    = (const float*)d_in[4];
    const float* net_W    = (const float*)d_in[5];
    const float* net_b    = (const float*)d_in[6];
    const float* dev_W    = (const float*)d_in[7];
    const float* dev_b    = (const float*)d_in[8];
    const float* pin_emb  = (const float*)d_in[9];
    const float* fc0_W    = (const float*)d_in[10];
    const float* fc0_b    = (const float*)d_in[11];
    const float* fc1_W    = (const float*)d_in[12];
    const float* fc1_b    = (const float*)d_in[13];
    const float* fc2_W    = (const float*)d_in[14];
    const float* fc2_b    = (const float*)d_in[15];
    const float* bn0_g    = (const float*)d_in[16];
    const float* bn0_b    = (const float*)d_in[17];
    const float* bn1_g    = (const float*)d_in[18];
    const float* bn1_b    = (const float*)d_in[19];
    float* out = (float*)d_out;

    float *p_pooled, *p_r0, *p_h0, *p_r1, *p_h1;
    cudaGetSymbolAddress((void**)&p_pooled, d_pooled);
    cudaGetSymbolAddress((void**)&p_r0, d_r0);
    cudaGetSymbolAddress((void**)&p_h0, d_h0);
    cudaGetSymbolAddress((void**)&p_r1, d_r1);
    cudaGetSymbolAddress((void**)&p_h1, d_h1);

    k_find_starts<<<(GG + 1 + 255) / 256, 256>>>(batch);
    k_stats<<<GG, 128>>>(nattr, ntype);
    k_pool<<<GG, 256>>>(x, net_W, net_b, dev_W, dev_b, pin_emb);
    k_gemm_bias_relu<<<dim3((DD / 2) / 64, GG / 64), 256>>>(p_pooled, fc0_W, fc0_b, p_r0, GG, DD / 2, DD);
    k_bn<<<(DD / 2) / 64, 256>>>(p_r0, bn0_g, bn0_b, p_h0, DD / 2);
    k_gemm_bias_relu<<<dim3((DD / 4) / 64, GG / 64), 256>>>(p_h0, fc1_W, fc1_b, p_r1, GG, DD / 4, DD / 2);
    k_bn<<<(DD / 4) / 64, 256>>>(p_r1, bn1_g, bn1_b, p_h1, DD / 4);
    k_head_out<<<(GG * 32 + 255) / 256, 256>>>(p_h1, fc2_W, fc2_b, y_reg, out, out_size);
}

// round 2
// speedup vs baseline: 2.1486x; 2.1486x over previous
#include <cuda_runtime.h>
#include <cuda_bf16.h>

#define NN 262144
#define DD 1024
#define GG 1024
#define NA 17
#define EPS 1e-5f
#define SPLITK 4

// ---------------- scratch (device globals; no allocation allowed) -------------
__device__ int   d_starts[GG + 1];
__device__ float d_stats[GG * 56];                 // a0[17], a1[17], c2[17], n0, n1
__device__ float d_pooled[GG * DD];                // 4 MB
__device__ float d_part[SPLITK * GG * (DD / 2)];   // 8 MB (split-K partials, reused fc0/fc1)
__device__ float d_r0[GG * (DD / 2)];              // combined relu(fc0)
__device__ float d_h0[GG * (DD / 2)];
__device__ float d_r1[GG * (DD / 4)];
__device__ float d_h1[GG * (DD / 4)];
__device__ float d_bnsum[16 * (DD / 2)];
__device__ float d_bnsq[16 * (DD / 2)];
__device__ float d_mean[DD / 2];
__device__ float d_rstd[DD / 2];

// ---------------- K1: segment starts via binary search ------------------------
__global__ void k_find_starts(const int* __restrict__ batch) {
    int i = blockIdx.x * blockDim.x + threadIdx.x;
    if (i > GG) return;
    int lo = 0, hi = NN;
    while (lo < hi) {
        int mid = (lo + hi) >> 1;
        if (batch[mid] < i) lo = mid + 1; else hi = mid;
    }
    d_starts[i] = lo;
}

// ---------------- K2: per-graph attr stats ------------------------------------
__global__ void k_stats(const float* __restrict__ attr, const int* __restrict__ ntype) {
    int gph = blockIdx.x;
    int s0 = d_starts[gph], s1 = d_starts[gph + 1];

    float a0[NA], a1[NA], c2[NA];
    #pragma unroll
    for (int k = 0; k < NA; k++) { a0[k] = 0.f; a1[k] = 0.f; c2[k] = 0.f; }
    float n0 = 0.f, n1 = 0.f;

    for (int r = s0 + threadIdx.x; r < s1; r += blockDim.x) {
        int t = ntype[r];
        const float* ar = attr + (long)r * NA;
        float av[NA];
        #pragma unroll
        for (int k = 0; k < NA; k++) av[k] = ar[k];
        if (t == 0) {
            n0 += 1.f;
            #pragma unroll
            for (int k = 0; k < NA; k++) a0[k] += av[k];
        } else if (t == 1) {
            n1 += 1.f;
            #pragma unroll
            for (int k = 0; k < NA; k++) a1[k] += av[k];
        } else if (t == 2) {
            int idx = (int)av[0];
            idx = idx < 0 ? 0 : (idx > NA - 1 ? NA - 1 : idx);
            #pragma unroll
            for (int k = 0; k < NA; k++) c2[k] += (k == idx) ? 1.f : 0.f;
        }
    }

    __shared__ float s_acc[56];
    for (int j = threadIdx.x; j < 56; j += blockDim.x) s_acc[j] = 0.f;
    __syncthreads();

    int lane = threadIdx.x & 31;
    #pragma unroll
    for (int k = 0; k < NA; k++) {
        float v = a0[k];
        #pragma unroll
        for (int o = 16; o; o >>= 1) v += __shfl_xor_sync(0xffffffffu, v, o);
        if (lane == 0) atomicAdd(&s_acc[k], v);
        v = a1[k];
        #pragma unroll
        for (int o = 16; o; o >>= 1) v += __shfl_xor_sync(0xffffffffu, v, o);
        if (lane == 0) atomicAdd(&s_acc[NA + k], v);
        v = c2[k];
        #pragma unroll
        for (int o = 16; o; o >>= 1) v += __shfl_xor_sync(0xffffffffu, v, o);
        if (lane == 0) atomicAdd(&s_acc[2 * NA + k], v);
    }
    {
        float v = n0;
        #pragma unroll
        for (int o = 16; o; o >>= 1) v += __shfl_xor_sync(0xffffffffu, v, o);
        if (lane == 0) atomicAdd(&s_acc[51], v);
        v = n1;
        #pragma unroll
        for (int o = 16; o; o >>= 1) v += __shfl_xor_sync(0xffffffffu, v, o);
        if (lane == 0) atomicAdd(&s_acc[52], v);
    }
    __syncthreads();
    for (int j = threadIdx.x; j < 56; j += blockDim.x) d_stats[gph * 56 + j] = s_acc[j];
}

// ---------------- K3: segment sum of x + fused tiny emb GEMM + mean ----------
__global__ void k_pool(const float* __restrict__ x,
                       const float* __restrict__ netW, const float* __restrict__ netb,
                       const float* __restrict__ devW, const float* __restrict__ devb,
                       const float* __restrict__ pinE) {
    int gph = blockIdx.x;
    int s0 = d_starts[gph], s1 = d_starts[gph + 1];

    __shared__ float st[56];
    for (int j = threadIdx.x; j < 56; j += 256) st[j] = d_stats[gph * 56 + j];
    __syncthreads();

    int c4 = threadIdx.x;
    const float4* x4 = (const float4*)x;
    float4 acc = make_float4(0.f, 0.f, 0.f, 0.f);

    #pragma unroll 4
    for (int r = s0; r < s1; r++) {
        float4 v = x4[(long)r * 256 + c4];
        acc.x += v.x; acc.y += v.y; acc.z += v.z; acc.w += v.w;
    }

    const float4* nW4 = (const float4*)netW;
    const float4* dW4 = (const float4*)devW;
    const float4* pE4 = (const float4*)pinE;
    float4 e = make_float4(0.f, 0.f, 0.f, 0.f);
    #pragma unroll
    for (int k = 0; k < NA; k++) {
        float4 wn = nW4[k * 256 + c4];
        float4 wd = dW4[k * 256 + c4];
        float4 wp = pE4[k * 256 + c4];
        float a0 = st[k], a1 = st[NA + k], cc = st[2 * NA + k];
        e.x += a0 * wn.x + a1 * wd.x + cc * wp.x;
        e.y += a0 * wn.y + a1 * wd.y + cc * wp.y;
        e.z += a0 * wn.z + a1 * wd.z + cc * wp.z;
        e.w += a0 * wn.w + a1 * wd.w + cc * wp.w;
    }
    float n0 = st[51], n1 = st[52];
    float4 nb = ((const float4*)netb)[c4];
    float4 db = ((const float4*)devb)[c4];
    e.x += n0 * nb.x + n1 * db.x;
    e.y += n0 * nb.y + n1 * db.y;
    e.z += n0 * nb.z + n1 * db.z;
    e.w += n0 * nb.w + n1 * db.w;

    float inv = 1.f / fmaxf((float)(s1 - s0), 1.f);
    float4 o;
    o.x = (acc.x + e.x) * inv;
    o.y = (acc.y + e.y) * inv;
    o.z = (acc.z + e.z) * inv;
    o.w = (acc.w + e.w) * inv;
    ((float4*)d_pooled)[(long)gph * 256 + c4] = o;
}

// ---------------- K4: split-K GEMM, 128x64 tile, 8x4/thread ------------------
// grid (N/64, M/128, SPLITK). Writes raw partial products (no bias).
__global__ void k_gemm_splitk(const float* __restrict__ A, const float* __restrict__ W,
                              float* __restrict__ part, int M, int N, int K, int kChunk) {
    __shared__ float As[16][128];
    __shared__ float Bs[16][68];
    int tid = threadIdx.x;
    int tx = tid & 15;       // col group (4 cols)
    int ty = tid >> 4;       // row group (8 rows)
    int n0 = blockIdx.x * 64, m0 = blockIdx.y * 128;
    int k0 = blockIdx.z * kChunk;
    float acc[8][4] = {};

    for (int kb = k0; kb < k0 + kChunk; kb += 16) {
        #pragma unroll
        for (int i = 0; i < 8; i++) {
            int idx = tid + i * 256;
            int m = idx >> 4, kk = idx & 15;
            As[kk][m] = A[(long)(m0 + m) * K + kb + kk];
        }
        #pragma unroll
        for (int i = 0; i < 4; i++) {
            int idx = tid + i * 256;
            int kk = idx >> 6, n = idx & 63;
            Bs[kk][n] = W[(long)(kb + kk) * N + n0 + n];
        }
        __syncthreads();
        #pragma unroll
        for (int kk = 0; kk < 16; kk++) {
            float4 a0 = *(const float4*)&As[kk][ty * 8];
            float4 a1 = *(const float4*)&As[kk][ty * 8 + 4];
            float4 b  = *(const float4*)&Bs[kk][tx * 4];
            float av[8] = {a0.x, a0.y, a0.z, a0.w, a1.x, a1.y, a1.z, a1.w};
            float bv[4] = {b.x, b.y, b.z, b.w};
            #pragma unroll
            for (int i = 0; i < 8; i++)
                #pragma unroll
                for (int j = 0; j < 4; j++)
                    acc[i][j] += av[i] * bv[j];
        }
        __syncthreads();
    }
    float* dst = part + (long)blockIdx.z * M * N;
    #pragma unroll
    for (int i = 0; i < 8; i++) {
        int m = m0 + ty * 8 + i;
        #pragma unroll
        for (int j = 0; j < 4; j++)
            dst[(long)m * N + n0 + tx * 4 + j] = acc[i][j];
    }
}

// ---------------- K5: combine split-K partials + bias + relu -----------------
__global__ void k_combine(const float* __restrict__ part, const float* __restrict__ bias,
                          float* __restrict__ out, int MN, int N) {
    int i4 = blockIdx.x * blockDim.x + threadIdx.x;
    if (i4 * 4 >= MN) return;
    float4 v = make_float4(0.f, 0.f, 0.f, 0.f);
    #pragma unroll
    for (int s = 0; s < SPLITK; s++) {
        float4 p = ((const float4*)(part + (long)s * MN))[i4];
        v.x += p.x; v.y += p.y; v.z += p.z; v.w += p.w;
    }
    int col = (i4 * 4) & (N - 1);   // N is power of 2
    float4 bb = *(const float4*)&bias[col];
    v.x = fmaxf(v.x + bb.x, 0.f);
    v.y = fmaxf(v.y + bb.y, 0.f);
    v.z = fmaxf(v.z + bb.z, 0.f);
    v.w = fmaxf(v.w + bb.w, 0.f);
    ((float4*)out)[i4] = v;
}

// ---------------- K6: per-column partial stats (64 cols x 128 rows/block) ----
__global__ void k_colstats(const float* __restrict__ V, int N) {
    int c0 = blockIdx.x * 64;
    int rchunk = blockIdx.y;           // 8 chunks of 128 rows
    int c = threadIdx.x & 63;
    int rg = threadIdx.x >> 6;         // 0..3
    float sum = 0.f, sq = 0.f;
    int rbase = rchunk * 128;
    for (int r = rbase + rg; r < rbase + 128; r += 4) {
        float v = V[(long)r * N + c0 + c];
        sum += v; sq += v * v;
    }
    __shared__ float ssum[4][64], ssq[4][64];
    ssum[rg][c] = sum; ssq[rg][c] = sq;
    __syncthreads();
    if (threadIdx.x < 64) {
        int cc = threadIdx.x;
        float s = ssum[0][cc] + ssum[1][cc] + ssum[2][cc] + ssum[3][cc];
        float q = ssq[0][cc] + ssq[1][cc] + ssq[2][cc] + ssq[3][cc];
        d_bnsum[rchunk * N + c0 + cc] = s;
        d_bnsq[rchunk * N + c0 + cc] = q;
    }
}

// ---------------- K7: finalize mean/rstd -------------------------------------
__global__ void k_bnfinal(int N) {
    int c = blockIdx.x * blockDim.x + threadIdx.x;
    if (c >= N) return;
    float s = 0.f, q = 0.f;
    #pragma unroll
    for (int ch = 0; ch < 8; ch++) { s += d_bnsum[ch * N + c]; q += d_bnsq[ch * N + c]; }
    float m = s / (float)GG;
    float var = q / (float)GG - m * m;
    d_mean[c] = m;
    d_rstd[c] = rsqrtf(var + EPS);
}

// ---------------- K8: apply BN ------------------------------------------------
__global__ void k_bnapply(const float* __restrict__ V, const float* __restrict__ g,
                          const float* __restrict__ b, float* __restrict__ H, int MN, int N) {
    int i4 = blockIdx.x * blockDim.x + threadIdx.x;
    if (i4 * 4 >= MN) return;
    int col = (i4 * 4) & (N - 1);
    float4 v = ((const float4*)V)[i4];
    float4 mm = *(const float4*)&d_mean[col];
    float4 rs = *(const float4*)&d_rstd[col];
    float4 gg = *(const float4*)&g[col];
    float4 bb = *(const float4*)&b[col];
    v.x = (v.x - mm.x) * rs.x * gg.x + bb.x;
    v.y = (v.y - mm.y) * rs.y * gg.y + bb.y;
    v.z = (v.z - mm.z) * rs.z * gg.z + bb.z;
    v.w = (v.w - mm.w) * rs.w * gg.w + bb.w;
    ((float4*)H)[i4] = v;
}

// ---------------- K9: fc2 dot(256) + output assembly --------------------------
__global__ void k_head_out(const float* __restrict__ H, const float* __restrict__ w,
                           const float* __restrict__ b, const float* __restrict__ y_reg,
                           float* __restrict__ out, int out_size) {
    int warp = (blockIdx.x * blockDim.x + threadIdx.x) >> 5;
    int lane = threadIdx.x & 31;
    if (warp >= GG) return;
    float s = 0.f;
    #pragma unroll
    for (int k = lane; k < DD / 4; k += 32) s += H[(long)warp * (DD / 4) + k] * w[k];
    #pragma unroll
    for (int o = 16; o; o >>= 1) s += __shfl_xor_sync(0xffffffffu, s, o);
    if (lane == 0) {
        out[warp] = s + b[0];
        if (out_size >= 2 * GG) out[GG + warp] = y_reg[warp];
    }
}

// ---------------- launch ------------------------------------------------------
extern "C" void kernel_launch(void* const* d_in, const int* in_sizes, int n_in,
                              void* d_out, int out_size) {
    const float* x        = (const float*)d_in[0];
    const float* nattr    = (const float*)d_in[1];
    const int*   ntype    = (const int*)d_in[2];
    const int*   batch    = (const int*)d_in[3];
    const float* y_reg    = (const float*)d_in[4];
    const float* net_W    = (const float*)d_in[5];
    const float* net_b    = (const float*)d_in[6];
    const float* dev_W    = (const float*)d_in[7];
    const float* dev_b    = (const float*)d_in[8];
    const float* pin_emb  = (const float*)d_in[9];
    const float* fc0_W    = (const float*)d_in[10];
    const float* fc0_b    = (const float*)d_in[11];
    const float* fc1_W    = (const float*)d_in[12];
    const float* fc1_b    = (const float*)d_in[13];
    const float* fc2_W    = (const float*)d_in[14];
    const float* fc2_b    = (const float*)d_in[15];
    const float* bn0_g    = (const float*)d_in[16];
    const float* bn0_b    = (const float*)d_in[17];
    const float* bn1_g    = (const float*)d_in[18];
    const float* bn1_b    = (const float*)d_in[19];
    float* out = (float*)d_out;

    float *p_pooled, *p_part, *p_r0, *p_h0, *p_r1, *p_h1;
    cudaGetSymbolAddress((void**)&p_pooled, d_pooled);
    cudaGetSymbolAddress((void**)&p_part, d_part);
    cudaGetSymbolAddress((void**)&p_r0, d_r0);
    cudaGetSymbolAddress((void**)&p_h0, d_h0);
    cudaGetSymbolAddress((void**)&p_r1, d_r1);
    cudaGetSymbolAddress((void**)&p_h1, d_h1);

    const int N0 = DD / 2;   // 512
    const int N1 = DD / 4;   // 256
    const int MN0 = GG * N0; // 524288
    const int MN1 = GG * N1; // 262144

    k_find_starts<<<(GG + 1 + 255) / 256, 256>>>(batch);
    k_stats<<<GG, 128>>>(nattr, ntype);
    k_pool<<<GG, 256>>>(x, net_W, net_b, dev_W, dev_b, pin_emb);

    // fc0: 1024x512x1024, split-K 4
    k_gemm_splitk<<<dim3(N0 / 64, GG / 128, SPLITK), 256>>>(p_pooled, fc0_W, p_part, GG, N0, DD, DD / SPLITK);
    k_combine<<<(MN0 / 4 + 255) / 256, 256>>>(p_part, fc0_b, p_r0, MN0, N0);
    k_colstats<<<dim3(N0 / 64, 8), 256>>>(p_r0, N0);
    k_bnfinal<<<(N0 + 255) / 256, 256>>>(N0);
    k_bnapply<<<(MN0 / 4 + 255) / 256, 256>>>(p_r0, bn0_g, bn0_b, p_h0, MN0, N0);

    // fc1: 1024x256x512, split-K 4
    k_gemm_splitk<<<dim3(N1 / 64, GG / 128, SPLITK), 256>>>(p_h0, fc1_W, p_part, GG, N1, N0, N0 / SPLITK);
    k_combine<<<(MN1 / 4 + 255) / 256, 256>>>(p_part, fc1_b, p_r1, MN1, N1);
    k_colstats<<<dim3(N1 / 64, 8), 256>>>(p_r1, N1);
    k_bnfinal<<<(N1 + 255) / 256, 256>>>(N1);
    k_bnapply<<<(MN1 / 4 + 255) / 256, 256>>>(p_r1, bn1_g, bn1_b, p_h1, MN1, N1);

    k_head_out<<<(GG * 32 + 255) / 256, 256>>>(p_h1, fc2_W, fc2_b, y_reg, out, out_size);
}